// round 1
// baseline (speedup 1.0000x reference)
#include <cuda_runtime.h>
#include <cuda_bf16.h>
#include <stdint.h>

// Problem constants (fixed by the reference)
#define NN 50000
#define EE 800000
#define DD 256
#define LL 3
#define GG 512
#define ND (LL * DD)   // 768

// Scratch (static device globals; no runtime allocation allowed)
__device__ float g_h[(size_t)NN * DD];
__device__ float g_agg[(size_t)NN * DD];
__device__ float g_t[(size_t)NN * DD];
__device__ int   g_counts[GG];

// ---------------------------------------------------------------------------
// Utility kernels
// ---------------------------------------------------------------------------
__global__ void copy_f4_kernel(float4* __restrict__ dst, const float4* __restrict__ src, int n4) {
    int i = blockIdx.x * blockDim.x + threadIdx.x;
    if (i < n4) dst[i] = src[i];
}

__global__ void zero_f_kernel(float* __restrict__ p, int n) {
    int i = blockIdx.x * blockDim.x + threadIdx.x;
    if (i < n) p[i] = 0.0f;
}

__global__ void zero_i_kernel(int* __restrict__ p, int n) {
    int i = blockIdx.x * blockDim.x + threadIdx.x;
    if (i < n) p[i] = 0;
}

__global__ void count_kernel(const int* __restrict__ batch) {
    int i = blockIdx.x * blockDim.x + threadIdx.x;
    if (i < NN) atomicAdd(&g_counts[batch[i]], 1);
}

// ---------------------------------------------------------------------------
// Edge scatter: agg[dst] += h[src]   (agg pre-initialized to h)
// thread t -> edge e = t/64, float4 chunk c = t%64
// ---------------------------------------------------------------------------
__global__ void scatter_kernel(const int* __restrict__ src, const int* __restrict__ dst,
                               const float* __restrict__ h, float* __restrict__ agg) {
    long long t = (long long)blockIdx.x * blockDim.x + threadIdx.x;
    const long long total = (long long)EE * 64;
    if (t >= total) return;
    int e = (int)(t >> 6);
    int c = (int)(t & 63) << 2;          // float offset within row, multiple of 4
    int s = __ldg(&src[e]);
    int d = __ldg(&dst[e]);
    float4 v = *(const float4*)(h + (size_t)s * DD + c);
    float* p = agg + (size_t)d * DD + c;
    atomicAdd(p + 0, v.x);
    atomicAdd(p + 1, v.y);
    atomicAdd(p + 2, v.z);
    atomicAdd(p + 3, v.w);
}

// ---------------------------------------------------------------------------
// Tiled fp32 GEMM + bias + ReLU:  C[M,256] = relu(A[M,256] @ W[256,256] + b)
// BM=64, BN=64, BK=16, 256 threads, 4x4 micro-tile.
// Optionally also writes the result into out2 with row stride 768 (node_embed).
// ---------------------------------------------------------------------------
#define BM 64
#define BN 64
#define BK 16

__global__ __launch_bounds__(256)
void gemm_relu_kernel(const float* __restrict__ A, const float* __restrict__ W,
                      const float* __restrict__ bias, float* __restrict__ C,
                      float* __restrict__ out2 /* may be null; stride ND */) {
    __shared__ float As[BK][BM];
    __shared__ float Bs[BK][BN];

    const int tid = threadIdx.x;
    const int tx = tid & 15;         // 0..15  (col group)
    const int ty = tid >> 4;         // 0..15  (row group)
    const int bm = blockIdx.x * BM;
    const int bn = blockIdx.y * BN;

    // A-tile load mapping: each thread loads one float4
    const int a_row = tid >> 2;            // 0..63
    const int a_k4  = (tid & 3) << 2;      // 0,4,8,12

    // B-tile load mapping: 64x16 floats = 16x64... tile is BK x BN = 16*64 floats
    // each thread loads one float4: row = tid/16 (0..15), col4 = (tid%16)*4
    const int b_row = tid >> 4;            // k index 0..15
    const int b_c4  = (tid & 15) << 2;

    float acc[4][4];
#pragma unroll
    for (int i = 0; i < 4; i++)
#pragma unroll
        for (int j = 0; j < 4; j++) acc[i][j] = 0.0f;

    for (int k0 = 0; k0 < DD; k0 += BK) {
        // Load A tile (with M bound check)
        int gr = bm + a_row;
        float4 av;
        if (gr < NN) av = *(const float4*)(A + (size_t)gr * DD + k0 + a_k4);
        else         av = make_float4(0.f, 0.f, 0.f, 0.f);
        As[a_k4 + 0][a_row] = av.x;
        As[a_k4 + 1][a_row] = av.y;
        As[a_k4 + 2][a_row] = av.z;
        As[a_k4 + 3][a_row] = av.w;

        // Load B tile
        float4 bv = *(const float4*)(W + (size_t)(k0 + b_row) * DD + bn + b_c4);
        *(float4*)&Bs[b_row][b_c4] = bv;

        __syncthreads();

#pragma unroll
        for (int k = 0; k < BK; k++) {
            float4 a = *(const float4*)&As[k][ty << 2];
            float4 b = *(const float4*)&Bs[k][tx << 2];
            acc[0][0] += a.x * b.x; acc[0][1] += a.x * b.y; acc[0][2] += a.x * b.z; acc[0][3] += a.x * b.w;
            acc[1][0] += a.y * b.x; acc[1][1] += a.y * b.y; acc[1][2] += a.y * b.z; acc[1][3] += a.y * b.w;
            acc[2][0] += a.z * b.x; acc[2][1] += a.z * b.y; acc[2][2] += a.z * b.z; acc[2][3] += a.z * b.w;
            acc[3][0] += a.w * b.x; acc[3][1] += a.w * b.y; acc[3][2] += a.w * b.z; acc[3][3] += a.w * b.w;
        }
        __syncthreads();
    }

    // Epilogue: bias + relu, store to C (stride 256) and optionally out2 (stride 768)
#pragma unroll
    for (int i = 0; i < 4; i++) {
        int r = bm + (ty << 2) + i;
        if (r >= NN) continue;
        int cbase = bn + (tx << 2);
        float4 o;
        o.x = fmaxf(acc[i][0] + __ldg(&bias[cbase + 0]), 0.0f);
        o.y = fmaxf(acc[i][1] + __ldg(&bias[cbase + 1]), 0.0f);
        o.z = fmaxf(acc[i][2] + __ldg(&bias[cbase + 2]), 0.0f);
        o.w = fmaxf(acc[i][3] + __ldg(&bias[cbase + 3]), 0.0f);
        *(float4*)(C + (size_t)r * DD + cbase) = o;
        if (out2) *(float4*)(out2 + (size_t)r * ND + cbase) = o;
    }
}

// ---------------------------------------------------------------------------
// Pooling: graph[batch[n], c] += node_embed[n, c]
// grid (NN, 3), block 256: one block per (node, 256-col chunk)
// ---------------------------------------------------------------------------
__global__ void pool_kernel(const int* __restrict__ batch,
                            const float* __restrict__ node_embed,
                            float* __restrict__ graph_embed) {
    int n = blockIdx.x;
    int c = blockIdx.y * 256 + threadIdx.x;
    int g = __ldg(&batch[n]);
    float v = node_embed[(size_t)n * ND + c];
    atomicAdd(&graph_embed[(size_t)g * ND + c], v);
}

__global__ void divide_kernel(float* __restrict__ graph_embed) {
    int i = blockIdx.x * blockDim.x + threadIdx.x;
    if (i >= GG * ND) return;
    int g = i / ND;
    int cnt = g_counts[g];
    float d = (float)(cnt > 0 ? cnt : 1);
    graph_embed[i] /= d;
}

// ---------------------------------------------------------------------------
// Launch
// ---------------------------------------------------------------------------
extern "C" void kernel_launch(void* const* d_in, const int* in_sizes, int n_in,
                              void* d_out, int out_size) {
    const float* x          = (const float*)d_in[0];
    const int*   edge_index = (const int*)d_in[1];   // [2, E]
    const int*   batch      = (const int*)d_in[2];   // [N]
    const float* Ws1        = (const float*)d_in[3]; // [3,256,256]
    const float* bs1        = (const float*)d_in[4]; // [3,256]
    const float* Ws2        = (const float*)d_in[5]; // [3,256,256]
    const float* bs2        = (const float*)d_in[6]; // [3,256]

    float* out = (float*)d_out;
    float* graph_embed = out;                       // [512, 768]
    float* node_embed  = out + (size_t)GG * ND;     // [50000, 768]

    float* h   = nullptr; cudaGetSymbolAddress((void**)&h,   g_h);
    float* agg = nullptr; cudaGetSymbolAddress((void**)&agg, g_agg);
    float* t   = nullptr; cudaGetSymbolAddress((void**)&t,   g_t);
    int* counts = nullptr; cudaGetSymbolAddress((void**)&counts, g_counts);

    const int* esrc = edge_index;
    const int* edst = edge_index + EE;

    const int n4 = NN * DD / 4;   // 3,276,800 float4s

    // h = x
    copy_f4_kernel<<<(n4 + 255) / 256, 256>>>((float4*)h, (const float4*)x, n4);

    // counts
    zero_i_kernel<<<(GG + 255) / 256, 256>>>(counts, GG);
    count_kernel<<<(NN + 255) / 256, 256>>>(batch);

    // zero graph_embed region of d_out
    zero_f_kernel<<<(GG * ND + 255) / 256, 256>>>(graph_embed, GG * ND);

    dim3 ggrid((NN + BM - 1) / BM, DD / BN);   // (782, 4)

    for (int l = 0; l < LL; l++) {
        // agg = h
        copy_f4_kernel<<<(n4 + 255) / 256, 256>>>((float4*)agg, (const float4*)h, n4);
        // agg[dst] += h[src]
        long long total = (long long)EE * 64;
        int sblocks = (int)((total + 255) / 256);
        scatter_kernel<<<sblocks, 256>>>(esrc, edst, h, agg);
        // t = relu(agg @ W1 + b1)
        gemm_relu_kernel<<<ggrid, 256>>>(agg, Ws1 + (size_t)l * DD * DD, bs1 + l * DD, t, nullptr);
        // h = relu(t @ W2 + b2); also write into node_embed[:, l*256:(l+1)*256]
        gemm_relu_kernel<<<ggrid, 256>>>(t, Ws2 + (size_t)l * DD * DD, bs2 + l * DD, h,
                                         node_embed + (size_t)l * DD);
    }

    // pooled sums + divide
    dim3 pgrid(NN, LL);
    pool_kernel<<<pgrid, 256>>>(batch, node_embed, graph_embed);
    divide_kernel<<<(GG * ND + 255) / 256, 256>>>(graph_embed);
}

// round 2
// speedup vs baseline: 1.9432x; 1.9432x over previous
#include <cuda_runtime.h>
#include <cuda_bf16.h>
#include <stdint.h>

#define NN 50000
#define EE 800000
#define DD 256
#define LL 3
#define GG 512
#define ND (LL * DD)   // 768

// Scratch (static device globals)
__device__ float g_h[(size_t)NN * DD];
__device__ float g_agg[(size_t)NN * DD];
__device__ float g_t[(size_t)NN * DD];
__device__ int   g_deg[NN];
__device__ int   g_off[NN + 1];
__device__ int   g_cur[NN];
__device__ int   g_csr[EE];      // src node per CSR slot (grouped by dst)
__device__ int   g_counts[GG];

// ---------------------------------------------------------------------------
// Small utility kernels
// ---------------------------------------------------------------------------
__global__ void zero_f_kernel(float* __restrict__ p, int n) {
    int i = blockIdx.x * blockDim.x + threadIdx.x;
    if (i < n) p[i] = 0.0f;
}
__global__ void zero_i_kernel(int* __restrict__ p, int n) {
    int i = blockIdx.x * blockDim.x + threadIdx.x;
    if (i < n) p[i] = 0;
}
__global__ void count_graph_kernel(const int* __restrict__ batch, int* __restrict__ counts) {
    int i = blockIdx.x * blockDim.x + threadIdx.x;
    if (i < NN) atomicAdd(&counts[batch[i]], 1);
}

// ---------------------------------------------------------------------------
// CSR build
// ---------------------------------------------------------------------------
__global__ void deg_kernel(const int* __restrict__ dst, int* __restrict__ deg) {
    int e = blockIdx.x * blockDim.x + threadIdx.x;
    if (e < EE) atomicAdd(&deg[dst[e]], 1);
}

// Single-block exclusive scan over NN ints -> off, cur.
__global__ void scan_kernel(const int* __restrict__ deg, int* __restrict__ off,
                            int* __restrict__ cur) {
    __shared__ int warp_sums[32];
    __shared__ int carry_s;
    const int tid = threadIdx.x;
    const int lane = tid & 31;
    const int wid = tid >> 5;
    if (tid == 0) carry_s = 0;
    __syncthreads();

    for (int base = 0; base < NN; base += 1024) {
        int i = base + tid;
        int v = (i < NN) ? deg[i] : 0;
        // warp inclusive scan
        int incl = v;
#pragma unroll
        for (int o = 1; o < 32; o <<= 1) {
            int t = __shfl_up_sync(0xFFFFFFFFu, incl, o);
            if (lane >= o) incl += t;
        }
        if (lane == 31) warp_sums[wid] = incl;
        __syncthreads();
        if (wid == 0) {
            int ws = warp_sums[lane];
#pragma unroll
            for (int o = 1; o < 32; o <<= 1) {
                int t = __shfl_up_sync(0xFFFFFFFFu, ws, o);
                if (lane >= o) ws += t;
            }
            warp_sums[lane] = ws;
        }
        __syncthreads();
        int excl = incl - v + (wid > 0 ? warp_sums[wid - 1] : 0) + carry_s;
        if (i < NN) { off[i] = excl; cur[i] = excl; }
        __syncthreads();
        if (tid == 1023) carry_s = excl + v;
        __syncthreads();
    }
    if (tid == 0) off[NN] = carry_s;
}

__global__ void fill_kernel(const int* __restrict__ src, const int* __restrict__ dst,
                            int* __restrict__ cur, int* __restrict__ csr) {
    int e = blockIdx.x * blockDim.x + threadIdx.x;
    if (e >= EE) return;
    int d = dst[e];
    int p = atomicAdd(&cur[d], 1);
    csr[p] = src[e];
}

// ---------------------------------------------------------------------------
// Gather aggregation: agg[n] = h[n] + sum_{j in in(n)} h[csr[j]]
// 64 threads/block (one float4 per thread), one node per block.
// ---------------------------------------------------------------------------
__global__ __launch_bounds__(64)
void gather_kernel(const float* __restrict__ hin, float* __restrict__ agg,
                   const int* __restrict__ off, const int* __restrict__ csr) {
    const int n = blockIdx.x;
    const int c4 = threadIdx.x;                     // 0..63
    const float4* __restrict__ h4 = (const float4*)hin;

    float4 acc = __ldg(&h4[(size_t)n * 64 + c4]);
    int j = off[n];
    const int e = off[n + 1];

    for (; j + 4 <= e; j += 4) {
        int i0 = __ldg(&csr[j + 0]);
        int i1 = __ldg(&csr[j + 1]);
        int i2 = __ldg(&csr[j + 2]);
        int i3 = __ldg(&csr[j + 3]);
        float4 v0 = __ldg(&h4[(size_t)i0 * 64 + c4]);
        float4 v1 = __ldg(&h4[(size_t)i1 * 64 + c4]);
        float4 v2 = __ldg(&h4[(size_t)i2 * 64 + c4]);
        float4 v3 = __ldg(&h4[(size_t)i3 * 64 + c4]);
        acc.x += v0.x + v1.x + v2.x + v3.x;
        acc.y += v0.y + v1.y + v2.y + v3.y;
        acc.z += v0.z + v1.z + v2.z + v3.z;
        acc.w += v0.w + v1.w + v2.w + v3.w;
    }
    for (; j < e; j++) {
        int i0 = __ldg(&csr[j]);
        float4 v0 = __ldg(&h4[(size_t)i0 * 64 + c4]);
        acc.x += v0.x; acc.y += v0.y; acc.z += v0.z; acc.w += v0.w;
    }
    ((float4*)agg)[(size_t)n * 64 + c4] = acc;
}

// ---------------------------------------------------------------------------
// GEMM + bias + ReLU: C[M,256] = relu(A[M,256] @ W[256,256] + b)
// 128x128x16 tile, 256 threads, 8x8 micro-tile, register-prefetch pipeline.
// ---------------------------------------------------------------------------
#define BM 128
#define BN 128
#define BK 16

__global__ __launch_bounds__(256)
void gemm_relu_kernel(const float* __restrict__ A, const float* __restrict__ W,
                      const float* __restrict__ bias, float* __restrict__ C,
                      float* __restrict__ out2 /* nullable; row stride ND */) {
    __shared__ float As[BK][BM];
    __shared__ float Bs[BK][BN];

    const int tid = threadIdx.x;
    const int bm = blockIdx.x * BM;
    const int bn = blockIdx.y * BN;

    // A tile load: row ar (0..127), k-quad ak in {0,8}
    const int ar = tid & 127;
    const int ak = (tid >> 7) * 8;
    // B tile load: k rows bk and bk+8, 4 cols at bn4
    const int bk = tid >> 5;                  // 0..7
    const int bn4 = (tid & 31) << 2;          // 0..124
    // compute micro-tile origin
    const int tm = (tid >> 4) << 3;           // 0..120
    const int tn = (tid & 15) << 3;           // 0..120

    const int grA = bm + ar;
    const bool okA = grA < NN;
    const float* __restrict__ Arow = A + (size_t)grA * DD;

    float acc[8][8];
#pragma unroll
    for (int i = 0; i < 8; i++)
#pragma unroll
        for (int j = 0; j < 8; j++) acc[i][j] = 0.0f;

    // prologue: load tile 0
    float4 a0, a1, b0, b1;
    {
        a0 = okA ? *(const float4*)(Arow + ak)     : make_float4(0.f,0.f,0.f,0.f);
        a1 = okA ? *(const float4*)(Arow + ak + 4) : make_float4(0.f,0.f,0.f,0.f);
        b0 = *(const float4*)(W + (size_t)(bk)     * DD + bn + bn4);
        b1 = *(const float4*)(W + (size_t)(bk + 8) * DD + bn + bn4);
    }

    for (int k0 = 0; k0 < DD; k0 += BK) {
        // store staged regs to smem
        As[ak + 0][ar] = a0.x; As[ak + 1][ar] = a0.y; As[ak + 2][ar] = a0.z; As[ak + 3][ar] = a0.w;
        As[ak + 4][ar] = a1.x; As[ak + 5][ar] = a1.y; As[ak + 6][ar] = a1.z; As[ak + 7][ar] = a1.w;
        *(float4*)&Bs[bk][bn4]     = b0;
        *(float4*)&Bs[bk + 8][bn4] = b1;
        __syncthreads();

        // prefetch next tile into regs
        const int kn = k0 + BK;
        if (kn < DD) {
            a0 = okA ? *(const float4*)(Arow + kn + ak)     : make_float4(0.f,0.f,0.f,0.f);
            a1 = okA ? *(const float4*)(Arow + kn + ak + 4) : make_float4(0.f,0.f,0.f,0.f);
            b0 = *(const float4*)(W + (size_t)(kn + bk)     * DD + bn + bn4);
            b1 = *(const float4*)(W + (size_t)(kn + bk + 8) * DD + bn + bn4);
        }

#pragma unroll
        for (int k = 0; k < BK; k++) {
            float4 x0 = *(const float4*)&As[k][tm];
            float4 x1 = *(const float4*)&As[k][tm + 4];
            float4 y0 = *(const float4*)&Bs[k][tn];
            float4 y1 = *(const float4*)&Bs[k][tn + 4];
            float av[8] = {x0.x, x0.y, x0.z, x0.w, x1.x, x1.y, x1.z, x1.w};
            float bv[8] = {y0.x, y0.y, y0.z, y0.w, y1.x, y1.y, y1.z, y1.w};
#pragma unroll
            for (int i = 0; i < 8; i++)
#pragma unroll
                for (int j = 0; j < 8; j++)
                    acc[i][j] += av[i] * bv[j];
        }
        __syncthreads();
    }

    // epilogue: bias + relu
    float bvals[8];
#pragma unroll
    for (int j = 0; j < 8; j++) bvals[j] = __ldg(&bias[bn + tn + j]);

#pragma unroll
    for (int i = 0; i < 8; i++) {
        int r = bm + tm + i;
        if (r >= NN) continue;
        float4 o0, o1;
        o0.x = fmaxf(acc[i][0] + bvals[0], 0.0f);
        o0.y = fmaxf(acc[i][1] + bvals[1], 0.0f);
        o0.z = fmaxf(acc[i][2] + bvals[2], 0.0f);
        o0.w = fmaxf(acc[i][3] + bvals[3], 0.0f);
        o1.x = fmaxf(acc[i][4] + bvals[4], 0.0f);
        o1.y = fmaxf(acc[i][5] + bvals[5], 0.0f);
        o1.z = fmaxf(acc[i][6] + bvals[6], 0.0f);
        o1.w = fmaxf(acc[i][7] + bvals[7], 0.0f);
        *(float4*)(C + (size_t)r * DD + bn + tn)     = o0;
        *(float4*)(C + (size_t)r * DD + bn + tn + 4) = o1;
        if (out2) {
            *(float4*)(out2 + (size_t)r * ND + bn + tn)     = o0;
            *(float4*)(out2 + (size_t)r * ND + bn + tn + 4) = o1;
        }
    }
}

// ---------------------------------------------------------------------------
// Pooling with run compression (batch is sorted): one atomic per graph
// transition per thread. grid (NN/128, ND/256), block 256.
// ---------------------------------------------------------------------------
__global__ __launch_bounds__(256)
void pool_kernel(const int* __restrict__ batch, const float* __restrict__ ne,
                 float* __restrict__ gev) {
    const int c = blockIdx.y * 256 + threadIdx.x;
    const int n0 = blockIdx.x * 128;
    int n1 = n0 + 128; if (n1 > NN) n1 = NN;

    int g = __ldg(&batch[n0]);
    float acc = 0.0f;
    for (int n = n0; n < n1; n++) {
        int gn = __ldg(&batch[n]);
        if (gn != g) {
            atomicAdd(&gev[(size_t)g * ND + c], acc);
            acc = 0.0f;
            g = gn;
        }
        acc += __ldg(&ne[(size_t)n * ND + c]);
    }
    atomicAdd(&gev[(size_t)g * ND + c], acc);
}

__global__ void divide_kernel(float* __restrict__ gev, const int* __restrict__ counts) {
    int i = blockIdx.x * blockDim.x + threadIdx.x;
    if (i >= GG * ND) return;
    int g = i / ND;
    int cnt = counts[g];
    gev[i] *= 1.0f / (float)(cnt > 0 ? cnt : 1);
}

// ---------------------------------------------------------------------------
// Launch
// ---------------------------------------------------------------------------
extern "C" void kernel_launch(void* const* d_in, const int* in_sizes, int n_in,
                              void* d_out, int out_size) {
    const float* x          = (const float*)d_in[0];
    const int*   edge_index = (const int*)d_in[1];
    const int*   batch      = (const int*)d_in[2];
    const float* Ws1        = (const float*)d_in[3];
    const float* bs1        = (const float*)d_in[4];
    const float* Ws2        = (const float*)d_in[5];
    const float* bs2        = (const float*)d_in[6];

    float* out = (float*)d_out;
    float* graph_embed = out;                     // [512, 768]
    float* node_embed  = out + (size_t)GG * ND;   // [50000, 768]

    float* h;   cudaGetSymbolAddress((void**)&h,   g_h);
    float* agg; cudaGetSymbolAddress((void**)&agg, g_agg);
    float* t;   cudaGetSymbolAddress((void**)&t,   g_t);
    int* deg;   cudaGetSymbolAddress((void**)&deg, g_deg);
    int* off;   cudaGetSymbolAddress((void**)&off, g_off);
    int* cur;   cudaGetSymbolAddress((void**)&cur, g_cur);
    int* csr;   cudaGetSymbolAddress((void**)&csr, g_csr);
    int* counts; cudaGetSymbolAddress((void**)&counts, g_counts);

    const int* esrc = edge_index;
    const int* edst = edge_index + EE;

    // CSR build
    zero_i_kernel<<<(NN + 255) / 256, 256>>>(deg, NN);
    deg_kernel<<<(EE + 255) / 256, 256>>>(edst, deg);
    scan_kernel<<<1, 1024>>>(deg, off, cur);
    fill_kernel<<<(EE + 255) / 256, 256>>>(esrc, edst, cur, csr);

    // graph counts + zero graph_embed
    zero_i_kernel<<<(GG + 255) / 256, 256>>>(counts, GG);
    count_graph_kernel<<<(NN + 255) / 256, 256>>>(batch, counts);
    zero_f_kernel<<<(GG * ND + 255) / 256, 256>>>(graph_embed, GG * ND);

    dim3 ggrid((NN + BM - 1) / BM, DD / BN);   // (391, 2)

    const float* hin = x;
    for (int l = 0; l < LL; l++) {
        gather_kernel<<<NN, 64>>>(hin, agg, off, csr);
        gemm_relu_kernel<<<ggrid, 256>>>(agg, Ws1 + (size_t)l * DD * DD, bs1 + l * DD, t, nullptr);
        gemm_relu_kernel<<<ggrid, 256>>>(t, Ws2 + (size_t)l * DD * DD, bs2 + l * DD, h,
                                         node_embed + (size_t)l * DD);
        hin = h;
    }

    dim3 pgrid((NN + 127) / 128, LL);
    pool_kernel<<<pgrid, 256>>>(batch, node_embed, graph_embed);
    divide_kernel<<<(GG * ND + 255) / 256, 256>>>(graph_embed, counts);
}

// round 5
// speedup vs baseline: 3.3876x; 1.7434x over previous
#include <cuda_runtime.h>
#include <cuda_bf16.h>
#include <stdint.h>

#define NN 50000
#define EE 800000
#define DD 256
#define LL 3
#define GG 512
#define ND (LL * DD)   // 768

// ---------------------------------------------------------------------------
// Device scratch (no runtime allocation allowed)
// ---------------------------------------------------------------------------
__device__ float g_h[(size_t)NN * DD];
__device__ float g_agg[(size_t)NN * DD];
__device__ float g_t[(size_t)NN * DD];
__device__ int   g_deg[NN];
__device__ int   g_off[NN + 1];
__device__ int   g_cur[NN];
__device__ int   g_csr[EE];
__device__ int   g_counts[GG];
// Transposed + bf16-split weights: [6][N=256][K=256]
__device__ __nv_bfloat16 g_wt_hi[6 * 256 * 256];
__device__ __nv_bfloat16 g_wt_lo[6 * 256 * 256];

// ---------------------------------------------------------------------------
// PTX helpers (sm_80-era features only: mma.sync / ldmatrix / cp.async)
// ---------------------------------------------------------------------------
__device__ __forceinline__ uint32_t smem_u32(const void* p) {
    uint32_t a;
    asm("{ .reg .u64 t; cvta.to.shared.u64 t, %1; cvt.u32.u64 %0, t; }" : "=r"(a) : "l"(p));
    return a;
}

__device__ __forceinline__ void ldsm4(uint32_t* r, uint32_t addr) {
    asm volatile("ldmatrix.sync.aligned.m8n8.x4.shared.b16 {%0,%1,%2,%3}, [%4];"
        : "=r"(r[0]), "=r"(r[1]), "=r"(r[2]), "=r"(r[3]) : "r"(addr));
}

__device__ __forceinline__ void mma_bf16(float* d, const uint32_t* a, const uint32_t* b) {
    asm volatile("mma.sync.aligned.m16n8k16.row.col.f32.bf16.bf16.f32 "
        "{%0,%1,%2,%3}, {%4,%5,%6,%7}, {%8,%9}, {%0,%1,%2,%3};"
        : "+f"(d[0]), "+f"(d[1]), "+f"(d[2]), "+f"(d[3])
        : "r"(a[0]), "r"(a[1]), "r"(a[2]), "r"(a[3]), "r"(b[0]), "r"(b[1]));
}

#define CP_ASYNC16(dst, src) \
    asm volatile("cp.async.cg.shared.global [%0], [%1], 16;" :: "r"(dst), "l"(src) : "memory")
#define CP_COMMIT() asm volatile("cp.async.commit_group;" ::: "memory")
#define CP_WAIT1()  asm volatile("cp.async.wait_group 1;" ::: "memory")
#define CP_WAIT0()  asm volatile("cp.async.wait_group 0;" ::: "memory")

// ---------------------------------------------------------------------------
// Small utility kernels
// ---------------------------------------------------------------------------
__global__ void zero_f_kernel(float* __restrict__ p, int n) {
    int i = blockIdx.x * blockDim.x + threadIdx.x;
    if (i < n) p[i] = 0.0f;
}
__global__ void zero_i_kernel(int* __restrict__ p, int n) {
    int i = blockIdx.x * blockDim.x + threadIdx.x;
    if (i < n) p[i] = 0;
}
__global__ void count_graph_kernel(const int* __restrict__ batch, int* __restrict__ counts) {
    int i = blockIdx.x * blockDim.x + threadIdx.x;
    if (i < NN) atomicAdd(&counts[batch[i]], 1);
}

// Transpose + bf16 hi/lo split of the 6 weight matrices.
// Input W is [K][N] row-major; output [N][K] row-major (col-major operand B).
__global__ void wprep_kernel(const float* __restrict__ Ws1, const float* __restrict__ Ws2,
                             __nv_bfloat16* __restrict__ wh, __nv_bfloat16* __restrict__ wl) {
    int i = blockIdx.x * blockDim.x + threadIdx.x;
    if (i >= 6 * 65536) return;
    int mat = i >> 16;
    int rem = i & 65535;
    int k = rem >> 8, n = rem & 255;
    const float* W = (mat < 3) ? (Ws1 + (size_t)mat * 65536) : (Ws2 + (size_t)(mat - 3) * 65536);
    float x = W[k * 256 + n];
    __nv_bfloat16 hi = __float2bfloat16(x);
    __nv_bfloat16 lo = __float2bfloat16(x - __bfloat162float(hi));
    size_t o = ((size_t)mat << 16) + (size_t)n * 256 + k;
    wh[o] = hi;
    wl[o] = lo;
}

// ---------------------------------------------------------------------------
// CSR build
// ---------------------------------------------------------------------------
__global__ void deg_kernel(const int* __restrict__ dst, int* __restrict__ deg) {
    int e = blockIdx.x * blockDim.x + threadIdx.x;
    if (e < EE) atomicAdd(&deg[dst[e]], 1);
}

__global__ void scan_kernel(const int* __restrict__ deg, int* __restrict__ off,
                            int* __restrict__ cur) {
    __shared__ int warp_sums[32];
    __shared__ int carry_s;
    const int tid = threadIdx.x;
    const int lane = tid & 31;
    const int wid = tid >> 5;
    if (tid == 0) carry_s = 0;
    __syncthreads();

    for (int base = 0; base < NN; base += 1024) {
        int i = base + tid;
        int v = (i < NN) ? deg[i] : 0;
        int incl = v;
#pragma unroll
        for (int o = 1; o < 32; o <<= 1) {
            int t = __shfl_up_sync(0xFFFFFFFFu, incl, o);
            if (lane >= o) incl += t;
        }
        if (lane == 31) warp_sums[wid] = incl;
        __syncthreads();
        if (wid == 0) {
            int ws = warp_sums[lane];
#pragma unroll
            for (int o = 1; o < 32; o <<= 1) {
                int t = __shfl_up_sync(0xFFFFFFFFu, ws, o);
                if (lane >= o) ws += t;
            }
            warp_sums[lane] = ws;
        }
        __syncthreads();
        int excl = incl - v + (wid > 0 ? warp_sums[wid - 1] : 0) + carry_s;
        if (i < NN) { off[i] = excl; cur[i] = excl; }
        __syncthreads();
        if (tid == 1023) carry_s = excl + v;
        __syncthreads();
    }
    if (tid == 0) off[NN] = carry_s;
}

__global__ void fill_kernel(const int* __restrict__ src, const int* __restrict__ dst,
                            int* __restrict__ cur, int* __restrict__ csr) {
    int e = blockIdx.x * blockDim.x + threadIdx.x;
    if (e >= EE) return;
    int d = dst[e];
    int p = atomicAdd(&cur[d], 1);
    csr[p] = src[e];
}

// ---------------------------------------------------------------------------
// Gather aggregation: agg[n] = h[n] + sum_{j in in(n)} h[csr[j]]
// ---------------------------------------------------------------------------
__global__ __launch_bounds__(64)
void gather_kernel(const float* __restrict__ hin, float* __restrict__ agg,
                   const int* __restrict__ off, const int* __restrict__ csr) {
    const int n = blockIdx.x;
    const int c4 = threadIdx.x;
    const float4* __restrict__ h4 = (const float4*)hin;

    float4 acc = __ldg(&h4[(size_t)n * 64 + c4]);
    int j = off[n];
    const int e = off[n + 1];

    for (; j + 4 <= e; j += 4) {
        int i0 = __ldg(&csr[j + 0]);
        int i1 = __ldg(&csr[j + 1]);
        int i2 = __ldg(&csr[j + 2]);
        int i3 = __ldg(&csr[j + 3]);
        float4 v0 = __ldg(&h4[(size_t)i0 * 64 + c4]);
        float4 v1 = __ldg(&h4[(size_t)i1 * 64 + c4]);
        float4 v2 = __ldg(&h4[(size_t)i2 * 64 + c4]);
        float4 v3 = __ldg(&h4[(size_t)i3 * 64 + c4]);
        acc.x += v0.x + v1.x + v2.x + v3.x;
        acc.y += v0.y + v1.y + v2.y + v3.y;
        acc.z += v0.z + v1.z + v2.z + v3.z;
        acc.w += v0.w + v1.w + v2.w + v3.w;
    }
    for (; j < e; j++) {
        int i0 = __ldg(&csr[j]);
        float4 v0 = __ldg(&h4[(size_t)i0 * 64 + c4]);
        acc.x += v0.x; acc.y += v0.y; acc.z += v0.z; acc.w += v0.w;
    }
    ((float4*)agg)[(size_t)n * 64 + c4] = acc;
}

// ---------------------------------------------------------------------------
// bf16x3 tensor-core GEMM: C[M,256] = relu(A[M,256] @ W[256,256] + b)
// CTA tile 128x128, 8 warps (warp tile 64x32), K chunk 32, double-buffered.
// A split hi/lo in-kernel; W pre-split (WH/WL are bf16 [N][K] row-major).
// ---------------------------------------------------------------------------
#define BM 128
#define BN 128
#define BK 32
#define BKP 40                     // padded row length in bf16 (80 bytes)
#define OF_AH 0
#define OF_AL 10240
#define OF_BH 20480
#define OF_BL 30720
#define BUFB  40960                // bytes per buffer
#define GEMM_SMEM (2 * BUFB)       // 81920

__global__ __launch_bounds__(256)
void gemm_bf16x3_kernel(const float* __restrict__ A,
                        const __nv_bfloat16* __restrict__ WH,
                        const __nv_bfloat16* __restrict__ WL,
                        const float* __restrict__ bias,
                        float* __restrict__ C, float* __restrict__ out2) {
    extern __shared__ char smem[];
    const uint32_t sb = smem_u32(smem);
    const int tid = threadIdx.x;
    const int lane = tid & 31;
    const int w = tid >> 5;
    const int wm = (w & 1) * 64;
    const int wn = (w >> 1) * 32;
    const int bm = blockIdx.x * BM;
    const int bn = blockIdx.y * BN;

    // per-thread A staging geometry (row fixed across chunks)
    int a_row[4], a_c4[4];
    const float* a_ptr[4];
    bool a_ok[4];
#pragma unroll
    for (int j = 0; j < 4; j++) {
        int idx = tid + j * 256;
        a_row[j] = idx >> 3;
        a_c4[j] = idx & 7;
        int gr = bm + a_row[j];
        a_ok[j] = gr < NN;
        a_ptr[j] = A + (size_t)(a_ok[j] ? gr : 0) * DD + a_c4[j] * 4;
    }

    // B cp.async geometry
    int b_half[4], b_n[4], b_seg[4];
#pragma unroll
    for (int j = 0; j < 4; j++) {
        int i = tid + j * 256;
        b_half[j] = i >> 9;
        int rem = i & 511;
        b_n[j] = rem >> 2;
        b_seg[j] = rem & 3;
    }

    float acc[4][4][4];
#pragma unroll
    for (int mi = 0; mi < 4; mi++)
#pragma unroll
        for (int nj = 0; nj < 4; nj++)
#pragma unroll
            for (int q = 0; q < 4; q++) acc[mi][nj][q] = 0.0f;

    // prologue: B chunk 0 -> buf0 via cp.async; A chunk 0 -> regs
    {
#pragma unroll
        for (int j = 0; j < 4; j++) {
            const __nv_bfloat16* src = (b_half[j] ? WL : WH) +
                ((size_t)(bn + b_n[j]) * DD + 0 + b_seg[j] * 8);
            uint32_t dst = sb + (b_half[j] ? OF_BL : OF_BH) + b_n[j] * 80 + b_seg[j] * 16;
            CP_ASYNC16(dst, src);
        }
        CP_COMMIT();
    }
    float4 areg[4];
#pragma unroll
    for (int j = 0; j < 4; j++)
        areg[j] = a_ok[j] ? *(const float4*)(a_ptr[j]) : make_float4(0.f, 0.f, 0.f, 0.f);

    const int frow = (lane & 7) + ((lane & 8) ? 8 : 0);   // A ldmatrix row sel
    const int fkc  = ((lane & 16) ? 8 : 0);               // A k half
    const int brow = (lane & 7) + ((lane & 16) ? 8 : 0);  // B ldmatrix row sel
    const int bkc  = ((lane & 8) ? 8 : 0);                // B k half

    for (int c = 0; c < 8; c++) {
        const uint32_t bufo = (uint32_t)(c & 1) * BUFB;

        // STS A chunk c (split hi/lo)
#pragma unroll
        for (int j = 0; j < 4; j++) {
            float4 v = areg[j];
            __nv_bfloat16 h0 = __float2bfloat16(v.x);
            __nv_bfloat16 h1 = __float2bfloat16(v.y);
            __nv_bfloat16 h2 = __float2bfloat16(v.z);
            __nv_bfloat16 h3 = __float2bfloat16(v.w);
            __nv_bfloat16 l0 = __float2bfloat16(v.x - __bfloat162float(h0));
            __nv_bfloat16 l1 = __float2bfloat16(v.y - __bfloat162float(h1));
            __nv_bfloat16 l2 = __float2bfloat16(v.z - __bfloat162float(h2));
            __nv_bfloat16 l3 = __float2bfloat16(v.w - __bfloat162float(h3));
            char* base = smem + bufo + a_row[j] * 80 + a_c4[j] * 8;
            ushort4 sh, sl;
            sh.x = __bfloat16_as_ushort(h0); sh.y = __bfloat16_as_ushort(h1);
            sh.z = __bfloat16_as_ushort(h2); sh.w = __bfloat16_as_ushort(h3);
            sl.x = __bfloat16_as_ushort(l0); sl.y = __bfloat16_as_ushort(l1);
            sl.z = __bfloat16_as_ushort(l2); sl.w = __bfloat16_as_ushort(l3);
            *(ushort4*)(base + OF_AH) = sh;
            *(ushort4*)(base + OF_AL) = sl;
        }

        if (c < 7) {
            const int kb2 = (c + 1) * BK;
            // prefetch A chunk c+1
#pragma unroll
            for (int j = 0; j < 4; j++)
                areg[j] = a_ok[j] ? *(const float4*)(a_ptr[j] + kb2)
                                  : make_float4(0.f, 0.f, 0.f, 0.f);
            // cp.async B chunk c+1 into the other buffer
            const uint32_t bo2 = (uint32_t)((c + 1) & 1) * BUFB;
#pragma unroll
            for (int j = 0; j < 4; j++) {
                const __nv_bfloat16* src = (b_half[j] ? WL : WH) +
                    ((size_t)(bn + b_n[j]) * DD + kb2 + b_seg[j] * 8);
                uint32_t dst = sb + bo2 + (b_half[j] ? OF_BL : OF_BH) + b_n[j] * 80 + b_seg[j] * 16;
                CP_ASYNC16(dst, src);
            }
            CP_COMMIT();
            CP_WAIT1();
        } else {
            CP_WAIT0();
        }
        __syncthreads();

        // MMA over chunk c: 2 k16-steps
        const uint32_t abh = sb + bufo + OF_AH;
        const uint32_t abl = sb + bufo + OF_AL;
        const uint32_t bbh = sb + bufo + OF_BH;
        const uint32_t bbl = sb + bufo + OF_BL;
#pragma unroll
        for (int ks = 0; ks < 2; ks++) {
            const int k0 = ks * 16;
            uint32_t ah[4][4], al[4][4], bh[4][2], bl[4][2];
#pragma unroll
            for (int mi = 0; mi < 4; mi++) {
                uint32_t off = (uint32_t)(wm + mi * 16 + frow) * 80 + (k0 + fkc) * 2;
                ldsm4(ah[mi], abh + off);
                ldsm4(al[mi], abl + off);
            }
#pragma unroll
            for (int p = 0; p < 2; p++) {
                uint32_t off = (uint32_t)(wn + p * 16 + brow) * 80 + (k0 + bkc) * 2;
                uint32_t t[4];
                ldsm4(t, bbh + off);
                bh[2 * p][0] = t[0]; bh[2 * p][1] = t[1];
                bh[2 * p + 1][0] = t[2]; bh[2 * p + 1][1] = t[3];
                ldsm4(t, bbl + off);
                bl[2 * p][0] = t[0]; bl[2 * p][1] = t[1];
                bl[2 * p + 1][0] = t[2]; bl[2 * p + 1][1] = t[3];
            }
#pragma unroll
            for (int mi = 0; mi < 4; mi++)
#pragma unroll
                for (int nj = 0; nj < 4; nj++) {
                    mma_bf16(acc[mi][nj], ah[mi], bh[nj]);
                    mma_bf16(acc[mi][nj], ah[mi], bl[nj]);
                    mma_bf16(acc[mi][nj], al[mi], bh[nj]);
                }
        }
        __syncthreads();
    }

    // epilogue: bias + relu
    const int g = lane >> 2;
    const int tg2 = (lane & 3) * 2;
#pragma unroll
    for (int mi = 0; mi < 4; mi++) {
        int r0 = bm + wm + mi * 16 + g;
        int r1 = r0 + 8;
        bool ok0 = r0 < NN, ok1 = r1 < NN;
#pragma unroll
        for (int nj = 0; nj < 4; nj++) {
            int col = bn + wn + nj * 8 + tg2;
            float b0 = __ldg(&bias[col]);
            float b1 = __ldg(&bias[col + 1]);
            if (ok0) {
                float2 v;
                v.x = fmaxf(acc[mi][nj][0] + b0, 0.0f);
                v.y = fmaxf(acc[mi][nj][1] + b1, 0.0f);
                *(float2*)(C + (size_t)r0 * DD + col) = v;
                if (out2) *(float2*)(out2 + (size_t)r0 * ND + col) = v;
            }
            if (ok1) {
                float2 v;
                v.x = fmaxf(acc[mi][nj][2] + b0, 0.0f);
                v.y = fmaxf(acc[mi][nj][3] + b1, 0.0f);
                *(float2*)(C + (size_t)r1 * DD + col) = v;
                if (out2) *(float2*)(out2 + (size_t)r1 * ND + col) = v;
            }
        }
    }
}

// ---------------------------------------------------------------------------
// Pooling with run compression (batch sorted)
// ---------------------------------------------------------------------------
__global__ __launch_bounds__(256)
void pool_kernel(const int* __restrict__ batch, const float* __restrict__ ne,
                 float* __restrict__ gev) {
    const int c = blockIdx.y * 256 + threadIdx.x;
    const int n0 = blockIdx.x * 128;
    int n1 = n0 + 128; if (n1 > NN) n1 = NN;

    int g = __ldg(&batch[n0]);
    float acc = 0.0f;
    for (int n = n0; n < n1; n++) {
        int gn = __ldg(&batch[n]);
        if (gn != g) {
            atomicAdd(&gev[(size_t)g * ND + c], acc);
            acc = 0.0f;
            g = gn;
        }
        acc += __ldg(&ne[(size_t)n * ND + c]);
    }
    atomicAdd(&gev[(size_t)g * ND + c], acc);
}

__global__ void divide_kernel(float* __restrict__ gev, const int* __restrict__ counts) {
    int i = blockIdx.x * blockDim.x + threadIdx.x;
    if (i >= GG * ND) return;
    int g = i / ND;
    int cnt = counts[g];
    gev[i] *= 1.0f / (float)(cnt > 0 ? cnt : 1);
}

// ---------------------------------------------------------------------------
// Launch
// ---------------------------------------------------------------------------
extern "C" void kernel_launch(void* const* d_in, const int* in_sizes, int n_in,
                              void* d_out, int out_size) {
    const float* x          = (const float*)d_in[0];
    const int*   edge_index = (const int*)d_in[1];
    const int*   batch      = (const int*)d_in[2];
    const float* Ws1        = (const float*)d_in[3];
    const float* bs1        = (const float*)d_in[4];
    const float* Ws2        = (const float*)d_in[5];
    const float* bs2        = (const float*)d_in[6];

    float* out = (float*)d_out;
    float* graph_embed = out;
    float* node_embed  = out + (size_t)GG * ND;

    float* h;    cudaGetSymbolAddress((void**)&h,    g_h);
    float* agg;  cudaGetSymbolAddress((void**)&agg,  g_agg);
    float* t;    cudaGetSymbolAddress((void**)&t,    g_t);
    int* deg;    cudaGetSymbolAddress((void**)&deg,  g_deg);
    int* off;    cudaGetSymbolAddress((void**)&off,  g_off);
    int* cur;    cudaGetSymbolAddress((void**)&cur,  g_cur);
    int* csr;    cudaGetSymbolAddress((void**)&csr,  g_csr);
    int* counts; cudaGetSymbolAddress((void**)&counts, g_counts);
    __nv_bfloat16* wth; cudaGetSymbolAddress((void**)&wth, g_wt_hi);
    __nv_bfloat16* wtl; cudaGetSymbolAddress((void**)&wtl, g_wt_lo);

    cudaFuncSetAttribute(gemm_bf16x3_kernel, cudaFuncAttributeMaxDynamicSharedMemorySize, GEMM_SMEM);

    const int* esrc = edge_index;
    const int* edst = edge_index + EE;

    // CSR build
    zero_i_kernel<<<(NN + 255) / 256, 256>>>(deg, NN);
    deg_kernel<<<(EE + 255) / 256, 256>>>(edst, deg);
    scan_kernel<<<1, 1024>>>(deg, off, cur);
    fill_kernel<<<(EE + 255) / 256, 256>>>(esrc, edst, cur, csr);

    // weight prep (transpose + bf16 split)
    wprep_kernel<<<(6 * 65536 + 255) / 256, 256>>>(Ws1, Ws2, wth, wtl);

    // graph counts + zero graph_embed
    zero_i_kernel<<<(GG + 255) / 256, 256>>>(counts, GG);
    count_graph_kernel<<<(NN + 255) / 256, 256>>>(batch, counts);
    zero_f_kernel<<<(GG * ND + 255) / 256, 256>>>(graph_embed, GG * ND);

    dim3 ggrid((NN + BM - 1) / BM, DD / BN);   // (391, 2)

    const float* hin = x;
    for (int l = 0; l < LL; l++) {
        gather_kernel<<<NN, 64>>>(hin, agg, off, csr);
        gemm_bf16x3_kernel<<<ggrid, 256, GEMM_SMEM>>>(
            agg, wth + (size_t)l * 65536, wtl + (size_t)l * 65536, bs1 + l * DD, t, nullptr);
        gemm_bf16x3_kernel<<<ggrid, 256, GEMM_SMEM>>>(
            t, wth + (size_t)(3 + l) * 65536, wtl + (size_t)(3 + l) * 65536, bs2 + l * DD, h,
            node_embed + (size_t)l * DD);
        hin = h;
    }

    dim3 pgrid((NN + 127) / 128, LL);
    pool_kernel<<<pgrid, 256>>>(batch, node_embed, graph_embed);
    divide_kernel<<<(GG * ND + 255) / 256, 256>>>(graph_embed, counts);
}